// round 11
// baseline (speedup 1.0000x reference)
#include <cuda_runtime.h>
#include <math.h>

#define BB 8
#define C4v 64
#define OQ 16
#define NNv 512
#define LL 12
#define CCv (OQ * C4v)   // 1024

typedef unsigned long long ull;

__device__ __forceinline__ ull pk(float lo, float hi) {
    ull r; asm("mov.b64 %0,{%1,%2};" : "=l"(r) : "f"(lo), "f"(hi)); return r;
}
__device__ __forceinline__ void upk(ull v, float& lo, float& hi) {
    asm("mov.b64 {%0,%1},%2;" : "=f"(lo), "=f"(hi) : "l"(v));
}
__device__ __forceinline__ ull fma2(ull a, ull b, ull c) {
    ull d; asm("fma.rn.f32x2 %0,%1,%2,%3;" : "=l"(d) : "l"(a), "l"(b), "l"(c)); return d;
}

// Scratch (device globals: allocation-free per harness rules)
__device__ float g_G[BB * NNv * CCv];   // [b][n][c'][c]  16.8 MB
__device__ float g_Fl[BB * NNv * OQ];   // [b][n][c']
__device__ float g_T[BB * NNv * NNv];   // [b][k][n]      8.4 MB
__device__ float g_H[BB * NNv * CCv];   // [b][k][cc]     16.8 MB
__device__ float g_xx[BB * OQ];
__device__ float g_yy[BB * OQ];
__device__ float g_invl2[BB];

__global__ void k_zero() {
    int t = threadIdx.x;
    if (t < BB * OQ) { g_xx[t] = 0.f; g_yy[t] = 0.f; }
}

// k1: Fc (local), Fl, G, norm partials. Block per (n, b), 128 threads.
__global__ void k1(const float* __restrict__ x, const float* __restrict__ Wc,
                   const float* __restrict__ bc) {
    int n = blockIdx.x, b = blockIdx.y;
    __shared__ float xs[C4v * LL];   // [c][l]
    __shared__ float Ws[OQ * C4v];   // [o][c]
    __shared__ float Fc[OQ * LL];    // [o][l]
    int t = threadIdx.x;

    for (int i = t; i < C4v * LL; i += 128) {
        int c = i / LL, l = i % LL;
        xs[i] = x[((b * C4v + c) * NNv + n) * LL + l];
    }
    for (int i = t; i < OQ * C4v; i += 128) Ws[i] = Wc[i];
    __syncthreads();

    for (int i = t; i < OQ * LL; i += 128) {
        int o = i / LL, l = i % LL;
        float s = bc[o];
        #pragma unroll 16
        for (int c = 0; c < C4v; c++) s += Ws[o * C4v + c] * xs[c * LL + l];
        Fc[i] = s;
    }
    __syncthreads();

    // G[b][n][o][c] = sum_l Fc[o][l] * x[c][l]
    for (int i = t; i < CCv; i += 128) {
        int o = i >> 6, c = i & 63;
        float s = 0.f;
        #pragma unroll
        for (int l = 0; l < LL; l++) s += Fc[o * LL + l] * xs[c * LL + l];
        g_G[(b * NNv + n) * CCv + i] = s;
    }
    if (t < OQ) {
        float fl = Fc[t * LL + (LL - 1)];
        g_Fl[(b * NNv + n) * OQ + t] = fl;
        float ys = 0.f;
        #pragma unroll
        for (int l = 0; l < LL; l++) { float v = Fc[t * LL + l]; ys += v * v; }
        atomicAdd(&g_xx[b * OQ + t], fl * fl);
        atomicAdd(&g_yy[b * OQ + t], ys);
    }
}

// k1b: inv_l2[b] = 1 / sum_c sqrt(xx)*sqrt(yy)
__global__ void k1b() {
    int b = blockIdx.x;
    int t = threadIdx.x;  // 32
    float v = 0.f;
    if (t < OQ) v = sqrtf(g_xx[b * OQ + t]) * sqrtf(g_yy[b * OQ + t]);
    #pragma unroll
    for (int s = 16; s > 0; s >>= 1) v += __shfl_down_sync(0xffffffffu, v, s);
    if (t == 0) g_invl2[b] = 1.0f / v;
}

// k2 (R8 winner): T[b][p][q] = relu(tanh(inv * max_c sum_o Fl[q][o]*G[p][o][c]))
// 64 threads; block covers (p-pair, 256-q half). The 128-reg Fl dup-pack set
// is amortized over TWO p rows (two G tables in smem) -> 8 FMA2 chains per
// broadcast LDS.64 pair.
__global__ void __launch_bounds__(64) k2() {
    int pp = blockIdx.x * 2, qh = blockIdx.y, b = blockIdx.z;
    __shared__ __align__(16) float Gs0[OQ * C4v];  // 4 KB
    __shared__ __align__(16) float Gs1[OQ * C4v];  // 4 KB
    int t = threadIdx.x;  // 64

    {
        const float4* s0 = (const float4*)(g_G + ((size_t)b * NNv + pp) * CCv);
        const float4* s1 = (const float4*)(g_G + ((size_t)b * NNv + pp + 1) * CCv);
        #pragma unroll
        for (int i = t; i < CCv / 4; i += 64) {
            ((float4*)Gs0)[i] = s0[i];
            ((float4*)Gs1)[i] = s1[i];
        }
    }

    // Fl dup packs for q = qh*256 + t + {0,64,128,192}
    ull fd[4][OQ];
    #pragma unroll
    for (int r = 0; r < 4; r++) {
        const float4* fp =
            (const float4*)(g_Fl + ((size_t)b * NNv + qh * 256 + t + r * 64) * OQ);
        #pragma unroll
        for (int i = 0; i < 4; i++) {
            float4 v = __ldg(fp + i);
            fd[r][4 * i + 0] = pk(v.x, v.x);
            fd[r][4 * i + 1] = pk(v.y, v.y);
            fd[r][4 * i + 2] = pk(v.z, v.z);
            fd[r][4 * i + 3] = pk(v.w, v.w);
        }
    }
    __syncthreads();

    float inv = g_invl2[b];
    float m0[4], m1[4];
    #pragma unroll
    for (int r = 0; r < 4; r++) { m0[r] = -1e30f; m1[r] = -1e30f; }

    for (int cp = 0; cp < C4v / 2; cp++) {   // 32 natural c-pairs
        ull a0[4] = {0, 0, 0, 0};
        ull a1[4] = {0, 0, 0, 0};
        #pragma unroll
        for (int o = 0; o < OQ; o++) {
            ull ga = *(const ull*)(Gs0 + o * C4v + 2 * cp);  // uniform LDS.64
            ull gb = *(const ull*)(Gs1 + o * C4v + 2 * cp);
            #pragma unroll
            for (int r = 0; r < 4; r++) {
                a0[r] = fma2(fd[r][o], ga, a0[r]);
                a1[r] = fma2(fd[r][o], gb, a1[r]);
            }
        }
        #pragma unroll
        for (int r = 0; r < 4; r++) {
            float lo, hi;
            upk(a0[r], lo, hi); m0[r] = fmaxf(m0[r], fmaxf(lo, hi));
            upk(a1[r], lo, hi); m1[r] = fmaxf(m1[r], fmaxf(lo, hi));
        }
    }
    float* T0 = g_T + ((size_t)b * NNv + pp) * NNv + qh * 256 + t;
    float* T1 = T0 + NNv;
    #pragma unroll
    for (int r = 0; r < 4; r++) {
        T0[r * 64] = fmaxf(tanhf(m0[r] * inv), 0.f);
        T1[r * 64] = fmaxf(tanhf(m1[r] * inv), 0.f);
    }
}

// k3: per-b SGEMM  H[k][cc] = sum_n T[k][n] * G[n][cc]
// 128x128 tile, Kt=16, 256 threads, 8x8 microtile (cc split 4+4), B staged
// DUP-PACKED as (T,T) ull pairs (pad 17 -> conflict-free uniform LDS.64, no
// per-kk ALU dup). Double-buffered smem, one __syncthreads per k-iter.
__global__ void __launch_bounds__(256, 2) k3() {
    int b = blockIdx.z;
    int cc0 = blockIdx.y * 128;
    int k0 = blockIdx.x * 128;
    const float* A  = g_G + (size_t)b * NNv * CCv;  // [n][cc]
    const float* Bm = g_T + (size_t)b * NNv * NNv;  // [k][n]
    float* Cm = g_H + (size_t)b * NNv * CCv;        // [k][cc]

    __shared__ float As[2][16][128];                // 16 KB
    __shared__ __align__(16) ull Bsd[2][128][17];   // 34.8 KB, (T,T) dup pairs
    int t = threadIdx.x;
    int tx = t & 15, ty = t >> 4;   // tx -> cc (4+4), ty -> k (8)

    int r_arow = t >> 5, r_acol = (t & 31) * 4;
    int r_arow2 = (t + 256) >> 5, r_acol2 = ((t + 256) & 31) * 4;
    int r_bk = t >> 2, r_bn = (t & 3) * 4;
    int r_bk2 = (t + 256) >> 2, r_bn2 = ((t + 256) & 3) * 4;

    // stage tile 0 into buffer 0
    {
        *(float4*)(&As[0][r_arow][r_acol]) =
            *(const float4*)(A + (size_t)r_arow * CCv + cc0 + r_acol);
        *(float4*)(&As[0][r_arow2][r_acol2]) =
            *(const float4*)(A + (size_t)r_arow2 * CCv + cc0 + r_acol2);
        float4 v = *(const float4*)(Bm + (size_t)(k0 + r_bk) * NNv + r_bn);
        Bsd[0][r_bk][r_bn + 0] = pk(v.x, v.x); Bsd[0][r_bk][r_bn + 1] = pk(v.y, v.y);
        Bsd[0][r_bk][r_bn + 2] = pk(v.z, v.z); Bsd[0][r_bk][r_bn + 3] = pk(v.w, v.w);
        v = *(const float4*)(Bm + (size_t)(k0 + r_bk2) * NNv + r_bn2);
        Bsd[0][r_bk2][r_bn2 + 0] = pk(v.x, v.x); Bsd[0][r_bk2][r_bn2 + 1] = pk(v.y, v.y);
        Bsd[0][r_bk2][r_bn2 + 2] = pk(v.z, v.z); Bsd[0][r_bk2][r_bn2 + 3] = pk(v.w, v.w);
    }
    __syncthreads();

    ull acc[4][8];
    #pragma unroll
    for (int i = 0; i < 4; i++)
        #pragma unroll
        for (int j = 0; j < 8; j++) acc[i][j] = 0ull;

    int buf = 0;
    for (int n0 = 0; n0 < NNv; n0 += 16) {
        if (n0 + 16 < NNv) {
            int nb = buf ^ 1, nn0 = n0 + 16;
            *(float4*)(&As[nb][r_arow][r_acol]) =
                *(const float4*)(A + (size_t)(nn0 + r_arow) * CCv + cc0 + r_acol);
            *(float4*)(&As[nb][r_arow2][r_acol2]) =
                *(const float4*)(A + (size_t)(nn0 + r_arow2) * CCv + cc0 + r_acol2);
            float4 v = *(const float4*)(Bm + (size_t)(k0 + r_bk) * NNv + nn0 + r_bn);
            Bsd[nb][r_bk][r_bn + 0] = pk(v.x, v.x); Bsd[nb][r_bk][r_bn + 1] = pk(v.y, v.y);
            Bsd[nb][r_bk][r_bn + 2] = pk(v.z, v.z); Bsd[nb][r_bk][r_bn + 3] = pk(v.w, v.w);
            v = *(const float4*)(Bm + (size_t)(k0 + r_bk2) * NNv + nn0 + r_bn2);
            Bsd[nb][r_bk2][r_bn2 + 0] = pk(v.x, v.x); Bsd[nb][r_bk2][r_bn2 + 1] = pk(v.y, v.y);
            Bsd[nb][r_bk2][r_bn2 + 2] = pk(v.z, v.z); Bsd[nb][r_bk2][r_bn2 + 3] = pk(v.w, v.w);
        }
        #pragma unroll
        for (int kk = 0; kk < 16; kk++) {
            float4 aA = *(const float4*)(&As[buf][kk][tx * 4]);
            float4 aB = *(const float4*)(&As[buf][kk][64 + tx * 4]);
            ull a0 = pk(aA.x, aA.y), a1 = pk(aA.z, aA.w);   // free pair renames
            ull a2 = pk(aB.x, aB.y), a3 = pk(aB.z, aB.w);
            #pragma unroll
            for (int j = 0; j < 8; j++) {
                ull bp = Bsd[buf][ty * 8 + j][kk];           // uniform LDS.64
                acc[0][j] = fma2(a0, bp, acc[0][j]);
                acc[1][j] = fma2(a1, bp, acc[1][j]);
                acc[2][j] = fma2(a2, bp, acc[2][j]);
                acc[3][j] = fma2(a3, bp, acc[3][j]);
            }
        }
        __syncthreads();
        buf ^= 1;
    }
    #pragma unroll
    for (int j = 0; j < 8; j++) {
        float4 v0, v1;
        upk(acc[0][j], v0.x, v0.y); upk(acc[1][j], v0.z, v0.w);
        upk(acc[2][j], v1.x, v1.y); upk(acc[3][j], v1.z, v1.w);
        float* dst = Cm + (size_t)(k0 + ty * 8 + j) * CCv + cc0;
        *(float4*)(dst + tx * 4) = v0;
        *(float4*)(dst + 64 + tx * 4) = v1;
    }
}

// k4: block = (32-k chunk, b), 256 threads. Stage Wg ONCE per block,
// two phases: xg then the 64x64x32 output GEMM.
__global__ void __launch_bounds__(256) k4(const float* __restrict__ Wg,
                                          const float* __restrict__ bg,
                                          float* __restrict__ out) {
    int k0 = blockIdx.x * 32, b = blockIdx.y;
    __shared__ float Wgs[C4v * 65];   // padded [o2][c], 16.6 KB
    __shared__ float xg[32][65];      // padded, 8.3 KB
    __shared__ float Flk[32][OQ];     // 2 KB
    int t = threadIdx.x;  // 256

    for (int i = t; i < C4v * C4v; i += 256)
        Wgs[(i >> 6) * 65 + (i & 63)] = Wg[i];
    if (t < 128)
        ((float4*)&Flk[0][0])[t] =
            ((const float4*)(g_Fl + ((size_t)b * NNv + k0) * OQ))[t];
    __syncthreads();

    float inv = g_invl2[b];
    {   // phase 1: thread -> (k = t/8, 8 c's)
        int k = t >> 3;
        int cg = (t & 7) * 8;
        const float4* Hrow =
            (const float4*)(g_H + ((size_t)b * NNv + k0 + k) * CCv);
        float s[8] = {0.f, 0.f, 0.f, 0.f, 0.f, 0.f, 0.f, 0.f};
        #pragma unroll 4
        for (int o = 0; o < OQ; o++) {
            float fl = Flk[k][o];
            float4 h0 = __ldg(Hrow + o * 16 + (cg >> 2));
            float4 h1 = __ldg(Hrow + o * 16 + (cg >> 2) + 1);
            s[0] += fl * h0.x; s[1] += fl * h0.y;
            s[2] += fl * h0.z; s[3] += fl * h0.w;
            s[4] += fl * h1.x; s[5] += fl * h1.y;
            s[6] += fl * h1.z; s[7] += fl * h1.w;
        }
        #pragma unroll
        for (int j = 0; j < 8; j++) xg[k][cg + j] = s[j] * inv;
    }
    __syncthreads();
    {   // phase 2: thread -> (o2 = t/4, 8 k's)
        int o2 = t >> 2;
        int kg = (t & 3) * 8;
        float s[8];
        float bias = bg[o2];
        #pragma unroll
        for (int j = 0; j < 8; j++) s[j] = bias;
        #pragma unroll 8
        for (int c = 0; c < C4v; c++) {
            float w = Wgs[o2 * 65 + c];
            #pragma unroll
            for (int j = 0; j < 8; j++) s[j] += w * xg[kg + j][c];
        }
        float* dst = out + ((size_t)b * C4v + o2) * NNv + k0 + kg;
        #pragma unroll
        for (int j = 0; j < 8; j++) dst[j] = s[j];
    }
}

extern "C" void kernel_launch(void* const* d_in, const int* in_sizes, int n_in,
                              void* d_out, int out_size) {
    const float* x  = (const float*)d_in[0];
    const float* Wc = (const float*)d_in[1];
    const float* bc = (const float*)d_in[2];
    const float* Wg = (const float*)d_in[3];
    const float* bg = (const float*)d_in[4];
    float* out = (float*)d_out;

    k_zero<<<1, 256>>>();
    k1<<<dim3(NNv, BB), 128>>>(x, Wc, bc);
    k1b<<<BB, 32>>>();
    k2<<<dim3(NNv / 2, 2, BB), 64>>>();
    k3<<<dim3(NNv / 128, CCv / 128, BB), 256>>>();
    k4<<<dim3(NNv / 32, BB), 256>>>(Wg, bg, out);
}

// round 12
// speedup vs baseline: 1.6526x; 1.6526x over previous
#include <cuda_runtime.h>
#include <math.h>

#define BB 8
#define C4v 64
#define OQ 16
#define NNv 512
#define LL 12
#define CCv (OQ * C4v)   // 1024

typedef unsigned long long ull;

__device__ __forceinline__ ull pk(float lo, float hi) {
    ull r; asm("mov.b64 %0,{%1,%2};" : "=l"(r) : "f"(lo), "f"(hi)); return r;
}
__device__ __forceinline__ void upk(ull v, float& lo, float& hi) {
    asm("mov.b64 {%0,%1},%2;" : "=f"(lo), "=f"(hi) : "l"(v));
}
__device__ __forceinline__ ull fma2(ull a, ull b, ull c) {
    ull d; asm("fma.rn.f32x2 %0,%1,%2,%3;" : "=l"(d) : "l"(a), "l"(b), "l"(c)); return d;
}

// Scratch (device globals: allocation-free per harness rules)
__device__ float g_G[BB * NNv * CCv];   // [b][n][c'][c]  16.8 MB
__device__ float g_Fl[BB * NNv * OQ];   // [b][n][c']
__device__ float g_T[BB * NNv * NNv];   // [b][k][n]      8.4 MB
__device__ float g_H[BB * NNv * CCv];   // [b][k][cc]     16.8 MB
__device__ float g_xx[BB * OQ];
__device__ float g_yy[BB * OQ];
__device__ float g_invl2[BB];

__global__ void k_zero() {
    int t = threadIdx.x;
    if (t < BB * OQ) { g_xx[t] = 0.f; g_yy[t] = 0.f; }
}

// k1: Fc (local), Fl, G, norm partials. Block per (n, b), 128 threads.
__global__ void k1(const float* __restrict__ x, const float* __restrict__ Wc,
                   const float* __restrict__ bc) {
    int n = blockIdx.x, b = blockIdx.y;
    __shared__ float xs[C4v * LL];   // [c][l]
    __shared__ float Ws[OQ * C4v];   // [o][c]
    __shared__ float Fc[OQ * LL];    // [o][l]
    int t = threadIdx.x;

    for (int i = t; i < C4v * LL; i += 128) {
        int c = i / LL, l = i % LL;
        xs[i] = x[((b * C4v + c) * NNv + n) * LL + l];
    }
    for (int i = t; i < OQ * C4v; i += 128) Ws[i] = Wc[i];
    __syncthreads();

    for (int i = t; i < OQ * LL; i += 128) {
        int o = i / LL, l = i % LL;
        float s = bc[o];
        #pragma unroll 16
        for (int c = 0; c < C4v; c++) s += Ws[o * C4v + c] * xs[c * LL + l];
        Fc[i] = s;
    }
    __syncthreads();

    // G[b][n][o][c] = sum_l Fc[o][l] * x[c][l]
    for (int i = t; i < CCv; i += 128) {
        int o = i >> 6, c = i & 63;
        float s = 0.f;
        #pragma unroll
        for (int l = 0; l < LL; l++) s += Fc[o * LL + l] * xs[c * LL + l];
        g_G[(b * NNv + n) * CCv + i] = s;
    }
    if (t < OQ) {
        float fl = Fc[t * LL + (LL - 1)];
        g_Fl[(b * NNv + n) * OQ + t] = fl;
        float ys = 0.f;
        #pragma unroll
        for (int l = 0; l < LL; l++) { float v = Fc[t * LL + l]; ys += v * v; }
        atomicAdd(&g_xx[b * OQ + t], fl * fl);
        atomicAdd(&g_yy[b * OQ + t], ys);
    }
}

// k1b: inv_l2[b] = 1 / sum_c sqrt(xx)*sqrt(yy)
__global__ void k1b() {
    int b = blockIdx.x;
    int t = threadIdx.x;  // 32
    float v = 0.f;
    if (t < OQ) v = sqrtf(g_xx[b * OQ + t]) * sqrtf(g_yy[b * OQ + t]);
    #pragma unroll
    for (int s = 16; s > 0; s >>= 1) v += __shfl_down_sync(0xffffffffu, v, s);
    if (t == 0) g_invl2[b] = 1.0f / v;
}

// k2 (R8 winner): T[b][p][q] = relu(tanh(inv * max_c sum_o Fl[q][o]*G[p][o][c]))
// 64 threads; block covers (p-pair, 256-q half). The 128-reg Fl dup-pack set
// is amortized over TWO p rows (two G tables in smem) -> 8 FMA2 chains per
// broadcast LDS.64 pair.
__global__ void __launch_bounds__(64) k2() {
    int pp = blockIdx.x * 2, qh = blockIdx.y, b = blockIdx.z;
    __shared__ __align__(16) float Gs0[OQ * C4v];  // 4 KB
    __shared__ __align__(16) float Gs1[OQ * C4v];  // 4 KB
    int t = threadIdx.x;  // 64

    {
        const float4* s0 = (const float4*)(g_G + ((size_t)b * NNv + pp) * CCv);
        const float4* s1 = (const float4*)(g_G + ((size_t)b * NNv + pp + 1) * CCv);
        #pragma unroll
        for (int i = t; i < CCv / 4; i += 64) {
            ((float4*)Gs0)[i] = s0[i];
            ((float4*)Gs1)[i] = s1[i];
        }
    }

    // Fl dup packs for q = qh*256 + t + {0,64,128,192}
    ull fd[4][OQ];
    #pragma unroll
    for (int r = 0; r < 4; r++) {
        const float4* fp =
            (const float4*)(g_Fl + ((size_t)b * NNv + qh * 256 + t + r * 64) * OQ);
        #pragma unroll
        for (int i = 0; i < 4; i++) {
            float4 v = __ldg(fp + i);
            fd[r][4 * i + 0] = pk(v.x, v.x);
            fd[r][4 * i + 1] = pk(v.y, v.y);
            fd[r][4 * i + 2] = pk(v.z, v.z);
            fd[r][4 * i + 3] = pk(v.w, v.w);
        }
    }
    __syncthreads();

    float inv = g_invl2[b];
    float m0[4], m1[4];
    #pragma unroll
    for (int r = 0; r < 4; r++) { m0[r] = -1e30f; m1[r] = -1e30f; }

    for (int cp = 0; cp < C4v / 2; cp++) {   // 32 natural c-pairs
        ull a0[4] = {0, 0, 0, 0};
        ull a1[4] = {0, 0, 0, 0};
        #pragma unroll
        for (int o = 0; o < OQ; o++) {
            ull ga = *(const ull*)(Gs0 + o * C4v + 2 * cp);  // uniform LDS.64
            ull gb = *(const ull*)(Gs1 + o * C4v + 2 * cp);
            #pragma unroll
            for (int r = 0; r < 4; r++) {
                a0[r] = fma2(fd[r][o], ga, a0[r]);
                a1[r] = fma2(fd[r][o], gb, a1[r]);
            }
        }
        #pragma unroll
        for (int r = 0; r < 4; r++) {
            float lo, hi;
            upk(a0[r], lo, hi); m0[r] = fmaxf(m0[r], fmaxf(lo, hi));
            upk(a1[r], lo, hi); m1[r] = fmaxf(m1[r], fmaxf(lo, hi));
        }
    }
    float* T0 = g_T + ((size_t)b * NNv + pp) * NNv + qh * 256 + t;
    float* T1 = T0 + NNv;
    #pragma unroll
    for (int r = 0; r < 4; r++) {
        T0[r * 64] = fmaxf(tanhf(m0[r] * inv), 0.f);
        T1[r * 64] = fmaxf(tanhf(m1[r] * inv), 0.f);
    }
}

// k3: per-b SGEMM  H[k][cc] = sum_n T[k][n] * G[n][cc]
// 128x128 tile, Kt=16, 256 threads, 8x8 microtile (cc split 4+4), B staged
// untransposed Bs[k][nn] floats (broadcast scalar LDS.32 reads). Double-
// buffered smem, one __syncthreads per k-iter.
__global__ void __launch_bounds__(256, 2) k3() {
    int b = blockIdx.z;
    int cc0 = blockIdx.y * 128;
    int k0 = blockIdx.x * 128;
    const float* A  = g_G + (size_t)b * NNv * CCv;  // [n][cc]
    const float* Bm = g_T + (size_t)b * NNv * NNv;  // [k][n]
    float* Cm = g_H + (size_t)b * NNv * CCv;        // [k][cc]

    __shared__ float As[2][16][128];
    __shared__ float Bs[2][128][21];
    int t = threadIdx.x;
    int tx = t & 15, ty = t >> 4;   // tx -> cc (4+4), ty -> k (8)

    int r_arow = t >> 5, r_acol = (t & 31) * 4;
    int r_arow2 = (t + 256) >> 5, r_acol2 = ((t + 256) & 31) * 4;
    int r_bk = t >> 2, r_bn = (t & 3) * 4;
    int r_bk2 = (t + 256) >> 2, r_bn2 = ((t + 256) & 3) * 4;

    // stage tile 0 into buffer 0
    {
        *(float4*)(&As[0][r_arow][r_acol]) =
            *(const float4*)(A + (size_t)r_arow * CCv + cc0 + r_acol);
        *(float4*)(&As[0][r_arow2][r_acol2]) =
            *(const float4*)(A + (size_t)r_arow2 * CCv + cc0 + r_acol2);
        float4 v = *(const float4*)(Bm + (size_t)(k0 + r_bk) * NNv + r_bn);
        Bs[0][r_bk][r_bn + 0] = v.x; Bs[0][r_bk][r_bn + 1] = v.y;
        Bs[0][r_bk][r_bn + 2] = v.z; Bs[0][r_bk][r_bn + 3] = v.w;
        v = *(const float4*)(Bm + (size_t)(k0 + r_bk2) * NNv + r_bn2);
        Bs[0][r_bk2][r_bn2 + 0] = v.x; Bs[0][r_bk2][r_bn2 + 1] = v.y;
        Bs[0][r_bk2][r_bn2 + 2] = v.z; Bs[0][r_bk2][r_bn2 + 3] = v.w;
    }
    __syncthreads();

    ull acc[4][8];
    #pragma unroll
    for (int i = 0; i < 4; i++)
        #pragma unroll
        for (int j = 0; j < 8; j++) acc[i][j] = 0ull;

    int buf = 0;
    for (int n0 = 0; n0 < NNv; n0 += 16) {
        if (n0 + 16 < NNv) {
            int nb = buf ^ 1, nn0 = n0 + 16;
            *(float4*)(&As[nb][r_arow][r_acol]) =
                *(const float4*)(A + (size_t)(nn0 + r_arow) * CCv + cc0 + r_acol);
            *(float4*)(&As[nb][r_arow2][r_acol2]) =
                *(const float4*)(A + (size_t)(nn0 + r_arow2) * CCv + cc0 + r_acol2);
            float4 v = *(const float4*)(Bm + (size_t)(k0 + r_bk) * NNv + nn0 + r_bn);
            Bs[nb][r_bk][r_bn + 0] = v.x; Bs[nb][r_bk][r_bn + 1] = v.y;
            Bs[nb][r_bk][r_bn + 2] = v.z; Bs[nb][r_bk][r_bn + 3] = v.w;
            v = *(const float4*)(Bm + (size_t)(k0 + r_bk2) * NNv + nn0 + r_bn2);
            Bs[nb][r_bk2][r_bn2 + 0] = v.x; Bs[nb][r_bk2][r_bn2 + 1] = v.y;
            Bs[nb][r_bk2][r_bn2 + 2] = v.z; Bs[nb][r_bk2][r_bn2 + 3] = v.w;
        }
        #pragma unroll
        for (int kk = 0; kk < 16; kk++) {
            float4 aA = *(const float4*)(&As[buf][kk][tx * 4]);
            float4 aB = *(const float4*)(&As[buf][kk][64 + tx * 4]);
            ull a0 = pk(aA.x, aA.y), a1 = pk(aA.z, aA.w);
            ull a2 = pk(aB.x, aB.y), a3 = pk(aB.z, aB.w);
            #pragma unroll
            for (int j = 0; j < 8; j++) {
                float bv = Bs[buf][ty * 8 + j][kk];               // broadcast
                ull bp = pk(bv, bv);
                acc[0][j] = fma2(a0, bp, acc[0][j]);
                acc[1][j] = fma2(a1, bp, acc[1][j]);
                acc[2][j] = fma2(a2, bp, acc[2][j]);
                acc[3][j] = fma2(a3, bp, acc[3][j]);
            }
        }
        __syncthreads();
        buf ^= 1;
    }
    #pragma unroll
    for (int j = 0; j < 8; j++) {
        float4 v0, v1;
        upk(acc[0][j], v0.x, v0.y); upk(acc[1][j], v0.z, v0.w);
        upk(acc[2][j], v1.x, v1.y); upk(acc[3][j], v1.z, v1.w);
        float* dst = Cm + (size_t)(k0 + ty * 8 + j) * CCv + cc0;
        *(float4*)(dst + tx * 4) = v0;
        *(float4*)(dst + 64 + tx * 4) = v1;
    }
}

// k4: block = (32-k chunk, b), 256 threads. Stage Wg ONCE per block,
// two phases: xg then the 64x64x32 output GEMM.
__global__ void __launch_bounds__(256) k4(const float* __restrict__ Wg,
                                          const float* __restrict__ bg,
                                          float* __restrict__ out) {
    int k0 = blockIdx.x * 32, b = blockIdx.y;
    __shared__ float Wgs[C4v * 65];   // padded [o2][c], 16.6 KB
    __shared__ float xg[32][65];      // padded, 8.3 KB
    __shared__ float Flk[32][OQ];     // 2 KB
    int t = threadIdx.x;  // 256

    for (int i = t; i < C4v * C4v; i += 256)
        Wgs[(i >> 6) * 65 + (i & 63)] = Wg[i];
    if (t < 128)
        ((float4*)&Flk[0][0])[t] =
            ((const float4*)(g_Fl + ((size_t)b * NNv + k0) * OQ))[t];
    __syncthreads();

    float inv = g_invl2[b];
    {   // phase 1: thread -> (k = t/8, 8 c's)
        int k = t >> 3;
        int cg = (t & 7) * 8;
        const float4* Hrow =
            (const float4*)(g_H + ((size_t)b * NNv + k0 + k) * CCv);
        float s[8] = {0.f, 0.f, 0.f, 0.f, 0.f, 0.f, 0.f, 0.f};
        #pragma unroll 4
        for (int o = 0; o < OQ; o++) {
            float fl = Flk[k][o];
            float4 h0 = __ldg(Hrow + o * 16 + (cg >> 2));
            float4 h1 = __ldg(Hrow + o * 16 + (cg >> 2) + 1);
            s[0] += fl * h0.x; s[1] += fl * h0.y;
            s[2] += fl * h0.z; s[3] += fl * h0.w;
            s[4] += fl * h1.x; s[5] += fl * h1.y;
            s[6] += fl * h1.z; s[7] += fl * h1.w;
        }
        #pragma unroll
        for (int j = 0; j < 8; j++) xg[k][cg + j] = s[j] * inv;
    }
    __syncthreads();
    {   // phase 2: thread -> (o2 = t/4, 8 k's)
        int o2 = t >> 2;
        int kg = (t & 3) * 8;
        float s[8];
        float bias = bg[o2];
        #pragma unroll
        for (int j = 0; j < 8; j++) s[j] = bias;
        #pragma unroll 8
        for (int c = 0; c < C4v; c++) {
            float w = Wgs[o2 * 65 + c];
            #pragma unroll
            for (int j = 0; j < 8; j++) s[j] += w * xg[kg + j][c];
        }
        float* dst = out + ((size_t)b * C4v + o2) * NNv + k0 + kg;
        #pragma unroll
        for (int j = 0; j < 8; j++) dst[j] = s[j];
    }
}

extern "C" void kernel_launch(void* const* d_in, const int* in_sizes, int n_in,
                              void* d_out, int out_size) {
    const float* x  = (const float*)d_in[0];
    const float* Wc = (const float*)d_in[1];
    const float* bc = (const float*)d_in[2];
    const float* Wg = (const float*)d_in[3];
    const float* bg = (const float*)d_in[4];
    float* out = (float*)d_out;

    k_zero<<<1, 256>>>();
    k1<<<dim3(NNv, BB), 128>>>(x, Wc, bc);
    k1b<<<BB, 32>>>();
    k2<<<dim3(NNv / 2, 2, BB), 64>>>();
    k3<<<dim3(NNv / 128, CCv / 128, BB), 256>>>();
    k4<<<dim3(NNv / 32, BB), 256>>>(Wg, bg, out);
}

// round 14
// speedup vs baseline: 2.3967x; 1.4503x over previous
#include <cuda_runtime.h>
#include <math.h>

#define BB 8
#define C4v 64
#define OQ 16
#define NNv 512
#define LL 12
#define CCv (OQ * C4v)   // 1024

typedef unsigned long long ull;

__device__ __forceinline__ ull pk(float lo, float hi) {
    ull r; asm("mov.b64 %0,{%1,%2};" : "=l"(r) : "f"(lo), "f"(hi)); return r;
}
__device__ __forceinline__ void upk(ull v, float& lo, float& hi) {
    asm("mov.b64 {%0,%1},%2;" : "=f"(lo), "=f"(hi) : "l"(v));
}
__device__ __forceinline__ ull fma2(ull a, ull b, ull c) {
    ull d; asm("fma.rn.f32x2 %0,%1,%2,%3;" : "=l"(d) : "l"(a), "l"(b), "l"(c)); return d;
}
__device__ __forceinline__ unsigned f2tf(float f) {
    unsigned u; asm("cvt.rna.tf32.f32 %0, %1;" : "=r"(u) : "f"(f)); return u;
}
__device__ __forceinline__ void mma_tf32(float* c, const unsigned* a, const unsigned* b) {
    asm volatile(
        "mma.sync.aligned.m16n8k8.row.col.f32.tf32.tf32.f32 "
        "{%0,%1,%2,%3}, {%4,%5,%6,%7}, {%8,%9}, {%0,%1,%2,%3};"
        : "+f"(c[0]), "+f"(c[1]), "+f"(c[2]), "+f"(c[3])
        : "r"(a[0]), "r"(a[1]), "r"(a[2]), "r"(a[3]), "r"(b[0]), "r"(b[1]));
}

// Scratch (device globals: allocation-free per harness rules)
__device__ float g_G[BB * NNv * CCv];   // [b][n][c'][c]  16.8 MB
__device__ float g_Fl[BB * NNv * OQ];   // [b][n][c']
__device__ float g_T[BB * NNv * NNv];   // [b][k][n]      8.4 MB
__device__ float g_H[BB * NNv * CCv];   // [b][k][cc]     16.8 MB
__device__ float g_xx[BB * OQ];
__device__ float g_yy[BB * OQ];
__device__ float g_invl2[BB];

__global__ void k_zero() {
    int t = threadIdx.x;
    if (t < BB * OQ) { g_xx[t] = 0.f; g_yy[t] = 0.f; }
}

// k1: Fc (local), Fl, G, norm partials. Block per (n, b), 128 threads.
__global__ void k1(const float* __restrict__ x, const float* __restrict__ Wc,
                   const float* __restrict__ bc) {
    int n = blockIdx.x, b = blockIdx.y;
    __shared__ float xs[C4v * LL];   // [c][l]
    __shared__ float Ws[OQ * C4v];   // [o][c]
    __shared__ float Fc[OQ * LL];    // [o][l]
    int t = threadIdx.x;

    for (int i = t; i < C4v * LL; i += 128) {
        int c = i / LL, l = i % LL;
        xs[i] = x[((b * C4v + c) * NNv + n) * LL + l];
    }
    for (int i = t; i < OQ * C4v; i += 128) Ws[i] = Wc[i];
    __syncthreads();

    for (int i = t; i < OQ * LL; i += 128) {
        int o = i / LL, l = i % LL;
        float s = bc[o];
        #pragma unroll 16
        for (int c = 0; c < C4v; c++) s += Ws[o * C4v + c] * xs[c * LL + l];
        Fc[i] = s;
    }
    __syncthreads();

    // G[b][n][o][c] = sum_l Fc[o][l] * x[c][l]
    for (int i = t; i < CCv; i += 128) {
        int o = i >> 6, c = i & 63;
        float s = 0.f;
        #pragma unroll
        for (int l = 0; l < LL; l++) s += Fc[o * LL + l] * xs[c * LL + l];
        g_G[(b * NNv + n) * CCv + i] = s;
    }
    if (t < OQ) {
        float fl = Fc[t * LL + (LL - 1)];
        g_Fl[(b * NNv + n) * OQ + t] = fl;
        float ys = 0.f;
        #pragma unroll
        for (int l = 0; l < LL; l++) { float v = Fc[t * LL + l]; ys += v * v; }
        atomicAdd(&g_xx[b * OQ + t], fl * fl);
        atomicAdd(&g_yy[b * OQ + t], ys);
    }
}

// k1b: inv_l2[b] = 1 / sum_c sqrt(xx)*sqrt(yy)
__global__ void k1b() {
    int b = blockIdx.x;
    int t = threadIdx.x;  // 32
    float v = 0.f;
    if (t < OQ) v = sqrtf(g_xx[b * OQ + t]) * sqrtf(g_yy[b * OQ + t]);
    #pragma unroll
    for (int s = 16; s > 0; s >>= 1) v += __shfl_down_sync(0xffffffffu, v, s);
    if (t == 0) g_invl2[b] = 1.0f / v;
}

// k2 (R8 winner): T[b][p][q] = relu(tanh(inv * max_c sum_o Fl[q][o]*G[p][o][c]))
// 64 threads; block covers (p-pair, 256-q half). The 128-reg Fl dup-pack set
// is amortized over TWO p rows (two G tables in smem) -> 8 FMA2 chains per
// broadcast LDS.64 pair.
__global__ void __launch_bounds__(64) k2() {
    int pp = blockIdx.x * 2, qh = blockIdx.y, b = blockIdx.z;
    __shared__ __align__(16) float Gs0[OQ * C4v];  // 4 KB
    __shared__ __align__(16) float Gs1[OQ * C4v];  // 4 KB
    int t = threadIdx.x;  // 64

    {
        const float4* s0 = (const float4*)(g_G + ((size_t)b * NNv + pp) * CCv);
        const float4* s1 = (const float4*)(g_G + ((size_t)b * NNv + pp + 1) * CCv);
        #pragma unroll
        for (int i = t; i < CCv / 4; i += 64) {
            ((float4*)Gs0)[i] = s0[i];
            ((float4*)Gs1)[i] = s1[i];
        }
    }

    // Fl dup packs for q = qh*256 + t + {0,64,128,192}
    ull fd[4][OQ];
    #pragma unroll
    for (int r = 0; r < 4; r++) {
        const float4* fp =
            (const float4*)(g_Fl + ((size_t)b * NNv + qh * 256 + t + r * 64) * OQ);
        #pragma unroll
        for (int i = 0; i < 4; i++) {
            float4 v = __ldg(fp + i);
            fd[r][4 * i + 0] = pk(v.x, v.x);
            fd[r][4 * i + 1] = pk(v.y, v.y);
            fd[r][4 * i + 2] = pk(v.z, v.z);
            fd[r][4 * i + 3] = pk(v.w, v.w);
        }
    }
    __syncthreads();

    float inv = g_invl2[b];
    float m0[4], m1[4];
    #pragma unroll
    for (int r = 0; r < 4; r++) { m0[r] = -1e30f; m1[r] = -1e30f; }

    for (int cp = 0; cp < C4v / 2; cp++) {   // 32 natural c-pairs
        ull a0[4] = {0, 0, 0, 0};
        ull a1[4] = {0, 0, 0, 0};
        #pragma unroll
        for (int o = 0; o < OQ; o++) {
            ull ga = *(const ull*)(Gs0 + o * C4v + 2 * cp);  // uniform LDS.64
            ull gb = *(const ull*)(Gs1 + o * C4v + 2 * cp);
            #pragma unroll
            for (int r = 0; r < 4; r++) {
                a0[r] = fma2(fd[r][o], ga, a0[r]);
                a1[r] = fma2(fd[r][o], gb, a1[r]);
            }
        }
        #pragma unroll
        for (int r = 0; r < 4; r++) {
            float lo, hi;
            upk(a0[r], lo, hi); m0[r] = fmaxf(m0[r], fmaxf(lo, hi));
            upk(a1[r], lo, hi); m1[r] = fmaxf(m1[r], fmaxf(lo, hi));
        }
    }
    float* T0 = g_T + ((size_t)b * NNv + pp) * NNv + qh * 256 + t;
    float* T1 = T0 + NNv;
    #pragma unroll
    for (int r = 0; r < 4; r++) {
        T0[r * 64] = fmaxf(tanhf(m0[r] * inv), 0.f);
        T1[r * 64] = fmaxf(tanhf(m1[r] * inv), 0.f);
    }
}

// k3: per-b GEMM on TENSOR CORES (tf32 HMMA):
//   H[k][cc] = sum_n T[k][n] * G[n][cc]   M=512(k), N=1024(cc), K=512(n)
// CTA 128x128, K-tile 32, 8 warps each 32(M)x64(N) via m16n8k8 tf32 mma.
// A tile = 128x32 = 1024 float4 -> FOUR stage passes (R13 bug: only 2).
__global__ void __launch_bounds__(256, 2) k3() {
    int b = blockIdx.z;
    int cc0 = blockIdx.y * 128;
    int k0 = blockIdx.x * 128;
    const float* Am = g_T + (size_t)b * NNv * NNv;  // [k][n]
    const float* Bm = g_G + (size_t)b * NNv * CCv;  // [n][cc]
    float* Cm = g_H + (size_t)b * NNv * CCv;        // [k][cc]

    __shared__ unsigned As[128][36];   // [m][k'] tf32, 18.4 KB
    __shared__ unsigned Bs[32][136];   // [k'][n] tf32, 17.4 KB

    int t = threadIdx.x;
    int lane = t & 31, w = t >> 5;
    int g = lane >> 2, tg = lane & 3;
    int wm = (w & 3) * 32;      // warp M offset (4 warps along M)
    int wn = (w >> 2) * 64;     // warp N offset (2 warps along N)

    float c[2][8][4];
    #pragma unroll
    for (int i = 0; i < 2; i++)
        #pragma unroll
        for (int j = 0; j < 8; j++)
            #pragma unroll
            for (int e = 0; e < 4; e++) c[i][j][e] = 0.f;

    for (int n0 = 0; n0 < NNv; n0 += 32) {
        // stage A: T[k0+row][n0 + 0..31]  (128 x 32 = 1024 float4, 4 passes)
        #pragma unroll
        for (int pass = 0; pass < 4; pass++) {
            int f = t + pass * 256;
            int row = f >> 3, c4 = (f & 7) * 4;
            float4 v = *(const float4*)(Am + (size_t)(k0 + row) * NNv + n0 + c4);
            As[row][c4 + 0] = f2tf(v.x); As[row][c4 + 1] = f2tf(v.y);
            As[row][c4 + 2] = f2tf(v.z); As[row][c4 + 3] = f2tf(v.w);
        }
        // stage B: G[n0+row][cc0 + 0..127]  (32 x 128 = 1024 float4, 4 passes)
        #pragma unroll
        for (int pass = 0; pass < 4; pass++) {
            int f = t + pass * 256;
            int row = f >> 5, c4 = (f & 31) * 4;
            float4 v = *(const float4*)(Bm + (size_t)(n0 + row) * CCv + cc0 + c4);
            Bs[row][c4 + 0] = f2tf(v.x); Bs[row][c4 + 1] = f2tf(v.y);
            Bs[row][c4 + 2] = f2tf(v.z); Bs[row][c4 + 3] = f2tf(v.w);
        }
        __syncthreads();
        #pragma unroll
        for (int k8 = 0; k8 < 4; k8++) {
            unsigned a[2][4], bb[8][2];
            #pragma unroll
            for (int i = 0; i < 2; i++) {
                int r = wm + i * 16 + g;
                a[i][0] = As[r][k8 * 8 + tg];
                a[i][1] = As[r + 8][k8 * 8 + tg];
                a[i][2] = As[r][k8 * 8 + tg + 4];
                a[i][3] = As[r + 8][k8 * 8 + tg + 4];
            }
            #pragma unroll
            for (int j = 0; j < 8; j++) {
                bb[j][0] = Bs[k8 * 8 + tg][wn + j * 8 + g];
                bb[j][1] = Bs[k8 * 8 + tg + 4][wn + j * 8 + g];
            }
            #pragma unroll
            for (int i = 0; i < 2; i++)
                #pragma unroll
                for (int j = 0; j < 8; j++)
                    mma_tf32(c[i][j], a[i], bb[j]);
        }
        __syncthreads();
    }
    // epilogue: c0,c1 -> (row, col+{0,1}); c2,c3 -> (row+8, ...)
    #pragma unroll
    for (int i = 0; i < 2; i++) {
        int r0 = k0 + wm + i * 16 + g;
        #pragma unroll
        for (int j = 0; j < 8; j++) {
            int col = cc0 + wn + j * 8 + tg * 2;
            *(float2*)(Cm + (size_t)r0 * CCv + col) =
                make_float2(c[i][j][0], c[i][j][1]);
            *(float2*)(Cm + (size_t)(r0 + 8) * CCv + col) =
                make_float2(c[i][j][2], c[i][j][3]);
        }
    }
}

// k4: block = (32-k chunk, b), 256 threads. Stage Wg ONCE per block,
// two phases: xg then the 64x64x32 output GEMM.
__global__ void __launch_bounds__(256) k4(const float* __restrict__ Wg,
                                          const float* __restrict__ bg,
                                          float* __restrict__ out) {
    int k0 = blockIdx.x * 32, b = blockIdx.y;
    __shared__ float Wgs[C4v * 65];   // padded [o2][c], 16.6 KB
    __shared__ float xg[32][65];      // padded, 8.3 KB
    __shared__ float Flk[32][OQ];     // 2 KB
    int t = threadIdx.x;  // 256

    for (int i = t; i < C4v * C4v; i += 256)
        Wgs[(i >> 6) * 65 + (i & 63)] = Wg[i];
    if (t < 128)
        ((float4*)&Flk[0][0])[t] =
            ((const float4*)(g_Fl + ((size_t)b * NNv + k0) * OQ))[t];
    __syncthreads();

    float inv = g_invl2[b];
    {   // phase 1: thread -> (k = t/8, 8 c's)
        int k = t >> 3;
        int cg = (t & 7) * 8;
        const float4* Hrow =
            (const float4*)(g_H + ((size_t)b * NNv + k0 + k) * CCv);
        float s[8] = {0.f, 0.f, 0.f, 0.f, 0.f, 0.f, 0.f, 0.f};
        #pragma unroll 4
        for (int o = 0; o < OQ; o++) {
            float fl = Flk[k][o];
            float4 h0 = __ldg(Hrow + o * 16 + (cg >> 2));
            float4 h1 = __ldg(Hrow + o * 16 + (cg >> 2) + 1);
            s[0] += fl * h0.x; s[1] += fl * h0.y;
            s[2] += fl * h0.z; s[3] += fl * h0.w;
            s[4] += fl * h1.x; s[5] += fl * h1.y;
            s[6] += fl * h1.z; s[7] += fl * h1.w;
        }
        #pragma unroll
        for (int j = 0; j < 8; j++) xg[k][cg + j] = s[j] * inv;
    }
    __syncthreads();
    {   // phase 2: thread -> (o2 = t/4, 8 k's)
        int o2 = t >> 2;
        int kg = (t & 3) * 8;
        float s[8];
        float bias = bg[o2];
        #pragma unroll
        for (int j = 0; j < 8; j++) s[j] = bias;
        #pragma unroll 8
        for (int c = 0; c < C4v; c++) {
            float w = Wgs[o2 * 65 + c];
            #pragma unroll
            for (int j = 0; j < 8; j++) s[j] += w * xg[kg + j][c];
        }
        float* dst = out + ((size_t)b * C4v + o2) * NNv + k0 + kg;
        #pragma unroll
        for (int j = 0; j < 8; j++) dst[j] = s[j];
    }
}

extern "C" void kernel_launch(void* const* d_in, const int* in_sizes, int n_in,
                              void* d_out, int out_size) {
    const float* x  = (const float*)d_in[0];
    const float* Wc = (const float*)d_in[1];
    const float* bc = (const float*)d_in[2];
    const float* Wg = (const float*)d_in[3];
    const float* bg = (const float*)d_in[4];
    float* out = (float*)d_out;

    k_zero<<<1, 256>>>();
    k1<<<dim3(NNv, BB), 128>>>(x, Wc, bc);
    k1b<<<BB, 32>>>();
    k2<<<dim3(NNv / 2, 2, BB), 64>>>();
    k3<<<dim3(NNv / 128, CCv / 128, BB), 256>>>();
    k4<<<dim3(NNv / 32, BB), 256>>>(Wg, bg, out);
}

// round 15
// speedup vs baseline: 3.3871x; 1.4133x over previous
#include <cuda_runtime.h>
#include <math.h>

#define BB 8
#define C4v 64
#define OQ 16
#define NNv 512
#define LL 12
#define CCv (OQ * C4v)   // 1024

typedef unsigned long long ull;

__device__ __forceinline__ unsigned f2tf(float f) {
    unsigned u; asm("cvt.rna.tf32.f32 %0, %1;" : "=r"(u) : "f"(f)); return u;
}
__device__ __forceinline__ void mma_tf32(float* c, const unsigned* a, const unsigned* b) {
    asm volatile(
        "mma.sync.aligned.m16n8k8.row.col.f32.tf32.tf32.f32 "
        "{%0,%1,%2,%3}, {%4,%5,%6,%7}, {%8,%9}, {%0,%1,%2,%3};"
        : "+f"(c[0]), "+f"(c[1]), "+f"(c[2]), "+f"(c[3])
        : "r"(a[0]), "r"(a[1]), "r"(a[2]), "r"(a[3]), "r"(b[0]), "r"(b[1]));
}

// Scratch (device globals: allocation-free per harness rules)
__device__ float g_G[BB * NNv * CCv];   // [b][n][c'][c]  16.8 MB
__device__ float g_Fl[BB * NNv * OQ];   // [b][n][c']
__device__ float g_T[BB * NNv * NNv];   // [b][k][n]      8.4 MB
__device__ float g_H[BB * NNv * CCv];   // [b][k][cc]     16.8 MB
__device__ float g_xx[BB * OQ];
__device__ float g_yy[BB * OQ];
__device__ float g_invl2[BB];

__global__ void k_zero() {
    int t = threadIdx.x;
    if (t < BB * OQ) { g_xx[t] = 0.f; g_yy[t] = 0.f; }
}

// k1: Fc (local), Fl, G, norm partials. Block per (n, b), 128 threads.
__global__ void k1(const float* __restrict__ x, const float* __restrict__ Wc,
                   const float* __restrict__ bc) {
    int n = blockIdx.x, b = blockIdx.y;
    __shared__ float xs[C4v * LL];   // [c][l]
    __shared__ float Ws[OQ * C4v];   // [o][c]
    __shared__ float Fc[OQ * LL];    // [o][l]
    int t = threadIdx.x;

    for (int i = t; i < C4v * LL; i += 128) {
        int c = i / LL, l = i % LL;
        xs[i] = x[((b * C4v + c) * NNv + n) * LL + l];
    }
    for (int i = t; i < OQ * C4v; i += 128) Ws[i] = Wc[i];
    __syncthreads();

    for (int i = t; i < OQ * LL; i += 128) {
        int o = i / LL, l = i % LL;
        float s = bc[o];
        #pragma unroll 16
        for (int c = 0; c < C4v; c++) s += Ws[o * C4v + c] * xs[c * LL + l];
        Fc[i] = s;
    }
    __syncthreads();

    // G[b][n][o][c] = sum_l Fc[o][l] * x[c][l]
    for (int i = t; i < CCv; i += 128) {
        int o = i >> 6, c = i & 63;
        float s = 0.f;
        #pragma unroll
        for (int l = 0; l < LL; l++) s += Fc[o * LL + l] * xs[c * LL + l];
        g_G[(b * NNv + n) * CCv + i] = s;
    }
    if (t < OQ) {
        float fl = Fc[t * LL + (LL - 1)];
        g_Fl[(b * NNv + n) * OQ + t] = fl;
        float ys = 0.f;
        #pragma unroll
        for (int l = 0; l < LL; l++) { float v = Fc[t * LL + l]; ys += v * v; }
        atomicAdd(&g_xx[b * OQ + t], fl * fl);
        atomicAdd(&g_yy[b * OQ + t], ys);
    }
}

// k1b: inv_l2[b] = 1 / sum_c sqrt(xx)*sqrt(yy)
__global__ void k1b() {
    int b = blockIdx.x;
    int t = threadIdx.x;  // 32
    float v = 0.f;
    if (t < OQ) v = sqrtf(g_xx[b * OQ + t]) * sqrtf(g_yy[b * OQ + t]);
    #pragma unroll
    for (int s = 16; s > 0; s >>= 1) v += __shfl_down_sync(0xffffffffu, v, s);
    if (t == 0) g_invl2[b] = 1.0f / v;
}

// k2 on TENSOR CORES: per (b,p): R[q][c] = sum_o Fl[q][o]*G[p][o][c]
// (512x64x16 GEMM), then T[p][q] = relu(tanh(inv * max_c R[q][c])).
// Block = 8 p's (one warp each), Fl staged once as tf32 (pad 20 ->
// conflict-free fragment loads), G[p] B-fragments in registers.
__global__ void __launch_bounds__(256) k2tc() {
    int p0 = blockIdx.x * 8, b = blockIdx.y;
    __shared__ unsigned Fls[NNv * 20];   // [q][o] tf32, 40 KB
    int t = threadIdx.x;
    int lane = t & 31, w = t >> 5;
    int g = lane >> 2, tg = lane & 3;
    int p = p0 + w;

    // stage Fl[b] (512 x 16) -> tf32 smem
    {
        const float4* src = (const float4*)(g_Fl + (size_t)b * NNv * OQ);
        for (int i = t; i < NNv * OQ / 4; i += 256) {
            float4 v = __ldg(src + i);
            int q = i >> 2, o4 = (i & 3) * 4;
            unsigned* dst = Fls + q * 20 + o4;
            dst[0] = f2tf(v.x); dst[1] = f2tf(v.y);
            dst[2] = f2tf(v.z); dst[3] = f2tf(v.w);
        }
    }

    // B fragments: G[b][p][o][c], 16x64, col-major tiles (k=o, n=c)
    const float* Gp = g_G + ((size_t)b * NNv + p) * CCv;
    unsigned bf[8][2][2];
    #pragma unroll
    for (int j = 0; j < 8; j++)
        #pragma unroll
        for (int ks = 0; ks < 2; ks++) {
            bf[j][ks][0] = f2tf(__ldg(Gp + (ks * 8 + tg) * C4v + j * 8 + g));
            bf[j][ks][1] = f2tf(__ldg(Gp + (ks * 8 + tg + 4) * C4v + j * 8 + g));
        }
    __syncthreads();

    float inv = g_invl2[b];
    float* Trow = g_T + ((size_t)b * NNv + p) * NNv;

    for (int mt = 0; mt < 32; mt++) {
        // A fragments from Fls (rows mt*16+g, mt*16+8+g; pad 20 -> no conflicts)
        unsigned a[2][4];
        int r = mt * 16 + g;
        #pragma unroll
        for (int ks = 0; ks < 2; ks++) {
            a[ks][0] = Fls[r * 20 + ks * 8 + tg];
            a[ks][1] = Fls[(r + 8) * 20 + ks * 8 + tg];
            a[ks][2] = Fls[r * 20 + ks * 8 + tg + 4];
            a[ks][3] = Fls[(r + 8) * 20 + ks * 8 + tg + 4];
        }
        float acc[8][4];
        #pragma unroll
        for (int j = 0; j < 8; j++)
            #pragma unroll
            for (int e = 0; e < 4; e++) acc[j][e] = 0.f;
        #pragma unroll
        for (int j = 0; j < 8; j++) {
            mma_tf32(acc[j], a[0], bf[j][0]);
            mma_tf32(acc[j], a[1], bf[j][1]);
        }
        // max over c: within-thread (8 N-tiles x 2 cols), then quad shfl
        float m0 = -1e30f, m1 = -1e30f;
        #pragma unroll
        for (int j = 0; j < 8; j++) {
            m0 = fmaxf(m0, fmaxf(acc[j][0], acc[j][1]));
            m1 = fmaxf(m1, fmaxf(acc[j][2], acc[j][3]));
        }
        m0 = fmaxf(m0, __shfl_xor_sync(0xffffffffu, m0, 1));
        m0 = fmaxf(m0, __shfl_xor_sync(0xffffffffu, m0, 2));
        m1 = fmaxf(m1, __shfl_xor_sync(0xffffffffu, m1, 1));
        m1 = fmaxf(m1, __shfl_xor_sync(0xffffffffu, m1, 2));
        if (tg == 0) {
            Trow[mt * 16 + g]     = fmaxf(tanhf(m0 * inv), 0.f);
            Trow[mt * 16 + 8 + g] = fmaxf(tanhf(m1 * inv), 0.f);
        }
    }
}

// k3: per-b GEMM on TENSOR CORES (tf32 HMMA):
//   H[k][cc] = sum_n T[k][n] * G[n][cc]   M=512(k), N=1024(cc), K=512(n)
__global__ void __launch_bounds__(256, 2) k3() {
    int b = blockIdx.z;
    int cc0 = blockIdx.y * 128;
    int k0 = blockIdx.x * 128;
    const float* Am = g_T + (size_t)b * NNv * NNv;  // [k][n]
    const float* Bm = g_G + (size_t)b * NNv * CCv;  // [n][cc]
    float* Cm = g_H + (size_t)b * NNv * CCv;        // [k][cc]

    __shared__ unsigned As[128][36];   // [m][k'] tf32
    __shared__ unsigned Bs[32][136];   // [k'][n] tf32

    int t = threadIdx.x;
    int lane = t & 31, w = t >> 5;
    int g = lane >> 2, tg = lane & 3;
    int wm = (w & 3) * 32;
    int wn = (w >> 2) * 64;

    float c[2][8][4];
    #pragma unroll
    for (int i = 0; i < 2; i++)
        #pragma unroll
        for (int j = 0; j < 8; j++)
            #pragma unroll
            for (int e = 0; e < 4; e++) c[i][j][e] = 0.f;

    for (int n0 = 0; n0 < NNv; n0 += 32) {
        #pragma unroll
        for (int pass = 0; pass < 4; pass++) {
            int f = t + pass * 256;
            int row = f >> 3, c4 = (f & 7) * 4;
            float4 v = *(const float4*)(Am + (size_t)(k0 + row) * NNv + n0 + c4);
            As[row][c4 + 0] = f2tf(v.x); As[row][c4 + 1] = f2tf(v.y);
            As[row][c4 + 2] = f2tf(v.z); As[row][c4 + 3] = f2tf(v.w);
        }
        #pragma unroll
        for (int pass = 0; pass < 4; pass++) {
            int f = t + pass * 256;
            int row = f >> 5, c4 = (f & 31) * 4;
            float4 v = *(const float4*)(Bm + (size_t)(n0 + row) * CCv + cc0 + c4);
            Bs[row][c4 + 0] = f2tf(v.x); Bs[row][c4 + 1] = f2tf(v.y);
            Bs[row][c4 + 2] = f2tf(v.z); Bs[row][c4 + 3] = f2tf(v.w);
        }
        __syncthreads();
        #pragma unroll
        for (int k8 = 0; k8 < 4; k8++) {
            unsigned a[2][4], bb[8][2];
            #pragma unroll
            for (int i = 0; i < 2; i++) {
                int r = wm + i * 16 + g;
                a[i][0] = As[r][k8 * 8 + tg];
                a[i][1] = As[r + 8][k8 * 8 + tg];
                a[i][2] = As[r][k8 * 8 + tg + 4];
                a[i][3] = As[r + 8][k8 * 8 + tg + 4];
            }
            #pragma unroll
            for (int j = 0; j < 8; j++) {
                bb[j][0] = Bs[k8 * 8 + tg][wn + j * 8 + g];
                bb[j][1] = Bs[k8 * 8 + tg + 4][wn + j * 8 + g];
            }
            #pragma unroll
            for (int i = 0; i < 2; i++)
                #pragma unroll
                for (int j = 0; j < 8; j++)
                    mma_tf32(c[i][j], a[i], bb[j]);
        }
        __syncthreads();
    }
    #pragma unroll
    for (int i = 0; i < 2; i++) {
        int r0 = k0 + wm + i * 16 + g;
        #pragma unroll
        for (int j = 0; j < 8; j++) {
            int col = cc0 + wn + j * 8 + tg * 2;
            *(float2*)(Cm + (size_t)r0 * CCv + col) =
                make_float2(c[i][j][0], c[i][j][1]);
            *(float2*)(Cm + (size_t)(r0 + 8) * CCv + col) =
                make_float2(c[i][j][2], c[i][j][3]);
        }
    }
}

// k4: block = (32-k chunk, b), 256 threads. Stage Wg ONCE per block,
// two phases: xg then the 64x64x32 output GEMM.
__global__ void __launch_bounds__(256) k4(const float* __restrict__ Wg,
                                          const float* __restrict__ bg,
                                          float* __restrict__ out) {
    int k0 = blockIdx.x * 32, b = blockIdx.y;
    __shared__ float Wgs[C4v * 65];   // padded [o2][c]
    __shared__ float xg[32][65];
    __shared__ float Flk[32][OQ];
    int t = threadIdx.x;  // 256

    for (int i = t; i < C4v * C4v; i += 256)
        Wgs[(i >> 6) * 65 + (i & 63)] = Wg[i];
    if (t < 128)
        ((float4*)&Flk[0][0])[t] =
            ((const float4*)(g_Fl + ((size_t)b * NNv + k0) * OQ))[t];
    __syncthreads();

    float inv = g_invl2[b];
    {   // phase 1: thread -> (k = t/8, 8 c's)
        int k = t >> 3;
        int cg = (t & 7) * 8;
        const float4* Hrow =
            (const float4*)(g_H + ((size_t)b * NNv + k0 + k) * CCv);
        float s[8] = {0.f, 0.f, 0.f, 0.f, 0.f, 0.f, 0.f, 0.f};
        #pragma unroll 4
        for (int o = 0; o < OQ; o++) {
            float fl = Flk[k][o];
            float4 h0 = __ldg(Hrow + o * 16 + (cg >> 2));
            float4 h1 = __ldg(Hrow + o * 16 + (cg >> 2) + 1);
            s[0] += fl * h0.x; s[1] += fl * h0.y;
            s[2] += fl * h0.z; s[3] += fl * h0.w;
            s[4] += fl * h1.x; s[5] += fl * h1.y;
            s[6] += fl * h1.z; s[7] += fl * h1.w;
        }
        #pragma unroll
        for (int j = 0; j < 8; j++) xg[k][cg + j] = s[j] * inv;
    }
    __syncthreads();
    {   // phase 2: thread -> (o2 = t/4, 8 k's)
        int o2 = t >> 2;
        int kg = (t & 3) * 8;
        float s[8];
        float bias = bg[o2];
        #pragma unroll
        for (int j = 0; j < 8; j++) s[j] = bias;
        #pragma unroll 8
        for (int c = 0; c < C4v; c++) {
            float w = Wgs[o2 * 65 + c];
            #pragma unroll
            for (int j = 0; j < 8; j++) s[j] += w * xg[kg + j][c];
        }
        float* dst = out + ((size_t)b * C4v + o2) * NNv + k0 + kg;
        #pragma unroll
        for (int j = 0; j < 8; j++) dst[j] = s[j];
    }
}

extern "C" void kernel_launch(void* const* d_in, const int* in_sizes, int n_in,
                              void* d_out, int out_size) {
    const float* x  = (const float*)d_in[0];
    const float* Wc = (const float*)d_in[1];
    const float* bc = (const float*)d_in[2];
    const float* Wg = (const float*)d_in[3];
    const float* bg = (const float*)d_in[4];
    float* out = (float*)d_out;

    k_zero<<<1, 256>>>();
    k1<<<dim3(NNv, BB), 128>>>(x, Wc, bc);
    k1b<<<BB, 32>>>();
    k2tc<<<dim3(NNv / 8, BB), 256>>>();
    k3<<<dim3(NNv / 128, CCv / 128, BB), 256>>>();
    k4<<<dim3(NNv / 32, BB), 256>>>(Wg, bg, out);
}

// round 16
// speedup vs baseline: 3.6612x; 1.0809x over previous
#include <cuda_runtime.h>
#include <math.h>

#define BB 8
#define C4v 64
#define OQ 16
#define NNv 512
#define LL 12
#define CCv (OQ * C4v)   // 1024

__device__ __forceinline__ unsigned f2tf(float f) {
    unsigned u; asm("cvt.rna.tf32.f32 %0, %1;" : "=r"(u) : "f"(f)); return u;
}
__device__ __forceinline__ float rnd_tf(float f) {
    return __uint_as_float(f2tf(f));
}
__device__ __forceinline__ void mma_tf32(float* c, const unsigned* a, const unsigned* b) {
    asm volatile(
        "mma.sync.aligned.m16n8k8.row.col.f32.tf32.tf32.f32 "
        "{%0,%1,%2,%3}, {%4,%5,%6,%7}, {%8,%9}, {%0,%1,%2,%3};"
        : "+f"(c[0]), "+f"(c[1]), "+f"(c[2]), "+f"(c[3])
        : "r"(a[0]), "r"(a[1]), "r"(a[2]), "r"(a[3]), "r"(b[0]), "r"(b[1]));
}
__device__ __forceinline__ void cpa16(void* dst_smem, const void* src) {
    unsigned d = (unsigned)__cvta_generic_to_shared(dst_smem);
    asm volatile("cp.async.cg.shared.global [%0], [%1], 16;" :: "r"(d), "l"(src));
}
// relu(tanh(x)) = tanh(max(x,0)); fast one-sided tanh for x>=0
__device__ __forceinline__ float tanh_relu(float x) {
    float m = fmaxf(x, 0.f);
    float e = __expf(-2.f * m);
    return __fdividef(1.f - e, 1.f + e);
}

// Scratch (device globals: allocation-free per harness rules)
__device__ float g_G[BB * NNv * CCv];   // [b][n][c'][c], tf32-rounded values
__device__ float g_Fl[BB * NNv * OQ];   // [b][n][c']
__device__ float g_T[BB * NNv * NNv];   // [b][k][n], tf32-rounded values
__device__ float g_H[BB * NNv * CCv];   // [b][k][cc]
__device__ float g_xx[BB * OQ];
__device__ float g_yy[BB * OQ];
__device__ float g_invl2[BB];

__global__ void k_zero() {
    int t = threadIdx.x;
    if (t < BB * OQ) { g_xx[t] = 0.f; g_yy[t] = 0.f; }
}

// k1: Fc (local), Fl, G (tf32-rounded), norm partials. Block per (n, b).
__global__ void k1(const float* __restrict__ x, const float* __restrict__ Wc,
                   const float* __restrict__ bc) {
    int n = blockIdx.x, b = blockIdx.y;
    __shared__ float xs[C4v * LL];   // [c][l]
    __shared__ float Ws[OQ * C4v];   // [o][c]
    __shared__ float Fc[OQ * LL];    // [o][l]
    int t = threadIdx.x;

    for (int i = t; i < C4v * LL; i += 128) {
        int c = i / LL, l = i % LL;
        xs[i] = x[((b * C4v + c) * NNv + n) * LL + l];
    }
    for (int i = t; i < OQ * C4v; i += 128) Ws[i] = Wc[i];
    __syncthreads();

    for (int i = t; i < OQ * LL; i += 128) {
        int o = i / LL, l = i % LL;
        float s = bc[o];
        #pragma unroll 16
        for (int c = 0; c < C4v; c++) s += Ws[o * C4v + c] * xs[c * LL + l];
        Fc[i] = s;
    }
    __syncthreads();

    // G[b][n][o][c] = sum_l Fc[o][l] * x[c][l]  (stored tf32-rounded, rna)
    for (int i = t; i < CCv; i += 128) {
        int o = i >> 6, c = i & 63;
        float s = 0.f;
        #pragma unroll
        for (int l = 0; l < LL; l++) s += Fc[o * LL + l] * xs[c * LL + l];
        g_G[(b * NNv + n) * CCv + i] = rnd_tf(s);
    }
    if (t < OQ) {
        float fl = Fc[t * LL + (LL - 1)];
        g_Fl[(b * NNv + n) * OQ + t] = fl;
        float ys = 0.f;
        #pragma unroll
        for (int l = 0; l < LL; l++) { float v = Fc[t * LL + l]; ys += v * v; }
        atomicAdd(&g_xx[b * OQ + t], fl * fl);
        atomicAdd(&g_yy[b * OQ + t], ys);
    }
}

// k1b: inv_l2[b] = 1 / sum_c sqrt(xx)*sqrt(yy)
__global__ void k1b() {
    int b = blockIdx.x;
    int t = threadIdx.x;  // 32
    float v = 0.f;
    if (t < OQ) v = sqrtf(g_xx[b * OQ + t]) * sqrtf(g_yy[b * OQ + t]);
    #pragma unroll
    for (int s = 16; s > 0; s >>= 1) v += __shfl_down_sync(0xffffffffu, v, s);
    if (t == 0) g_invl2[b] = 1.0f / v;
}

// k2 on TENSOR CORES: per (b,p): R[q][c] = sum_o Fl[q][o]*G[p][o][c],
// then T[p][q] = relu(tanh(inv * max_c R)). 2 p per warp (16 p per block);
// A-frags from Fls (pad 20, conflict-free) amortized over both p's.
// T stored tf32-rounded for k3's cp.async path.
__global__ void __launch_bounds__(256, 2) k2tc() {
    int p0 = blockIdx.x * 16, b = blockIdx.y;
    __shared__ unsigned Fls[NNv * 20];   // [q][o] tf32, 40 KB
    int t = threadIdx.x;
    int lane = t & 31, w = t >> 5;
    int g = lane >> 2, tg = lane & 3;
    int pA = p0 + 2 * w, pB = pA + 1;

    {
        const float4* src = (const float4*)(g_Fl + (size_t)b * NNv * OQ);
        for (int i = t; i < NNv * OQ / 4; i += 256) {
            float4 v = __ldg(src + i);
            int q = i >> 2, o4 = (i & 3) * 4;
            unsigned* dst = Fls + q * 20 + o4;
            dst[0] = f2tf(v.x); dst[1] = f2tf(v.y);
            dst[2] = f2tf(v.z); dst[3] = f2tf(v.w);
        }
    }

    // B fragments for both p's (G pre-rounded; f2tf idempotent)
    const float* GA = g_G + ((size_t)b * NNv + pA) * CCv;
    const float* GB = g_G + ((size_t)b * NNv + pB) * CCv;
    unsigned bfA[8][2][2], bfB[8][2][2];
    #pragma unroll
    for (int j = 0; j < 8; j++)
        #pragma unroll
        for (int ks = 0; ks < 2; ks++) {
            bfA[j][ks][0] = __float_as_uint(__ldg(GA + (ks * 8 + tg) * C4v + j * 8 + g));
            bfA[j][ks][1] = __float_as_uint(__ldg(GA + (ks * 8 + tg + 4) * C4v + j * 8 + g));
            bfB[j][ks][0] = __float_as_uint(__ldg(GB + (ks * 8 + tg) * C4v + j * 8 + g));
            bfB[j][ks][1] = __float_as_uint(__ldg(GB + (ks * 8 + tg + 4) * C4v + j * 8 + g));
        }
    __syncthreads();

    float inv = g_invl2[b];
    float* TrA = g_T + ((size_t)b * NNv + pA) * NNv;
    float* TrB = g_T + ((size_t)b * NNv + pB) * NNv;

    for (int mt = 0; mt < 32; mt++) {
        unsigned a[2][4];
        int r = mt * 16 + g;
        #pragma unroll
        for (int ks = 0; ks < 2; ks++) {
            a[ks][0] = Fls[r * 20 + ks * 8 + tg];
            a[ks][1] = Fls[(r + 8) * 20 + ks * 8 + tg];
            a[ks][2] = Fls[r * 20 + ks * 8 + tg + 4];
            a[ks][3] = Fls[(r + 8) * 20 + ks * 8 + tg + 4];
        }
        #pragma unroll
        for (int pp = 0; pp < 2; pp++) {
            float acc[8][4];
            #pragma unroll
            for (int j = 0; j < 8; j++)
                #pragma unroll
                for (int e = 0; e < 4; e++) acc[j][e] = 0.f;
            #pragma unroll
            for (int j = 0; j < 8; j++) {
                if (pp == 0) {
                    mma_tf32(acc[j], a[0], bfA[j][0]);
                    mma_tf32(acc[j], a[1], bfA[j][1]);
                } else {
                    mma_tf32(acc[j], a[0], bfB[j][0]);
                    mma_tf32(acc[j], a[1], bfB[j][1]);
                }
            }
            float m0 = -1e30f, m1 = -1e30f;
            #pragma unroll
            for (int j = 0; j < 8; j++) {
                m0 = fmaxf(m0, fmaxf(acc[j][0], acc[j][1]));
                m1 = fmaxf(m1, fmaxf(acc[j][2], acc[j][3]));
            }
            m0 = fmaxf(m0, __shfl_xor_sync(0xffffffffu, m0, 1));
            m0 = fmaxf(m0, __shfl_xor_sync(0xffffffffu, m0, 2));
            m1 = fmaxf(m1, __shfl_xor_sync(0xffffffffu, m1, 1));
            m1 = fmaxf(m1, __shfl_xor_sync(0xffffffffu, m1, 2));
            if (tg == 0) {
                float* Tr = pp ? TrB : TrA;
                Tr[mt * 16 + g]     = rnd_tf(tanh_relu(m0 * inv));
                Tr[mt * 16 + 8 + g] = rnd_tf(tanh_relu(m1 * inv));
            }
        }
    }
}

// k3: per-b tf32 GEMM  H[k][cc] = sum_n T[k][n] * G[n][cc].
// Operands pre-rounded to tf32 at producers -> staging is pure cp.async
// (no cvt/STS), 2-stage double buffer overlapping copies with MMA.
__global__ void __launch_bounds__(256, 2) k3() {
    int b = blockIdx.z;
    int cc0 = blockIdx.y * 128;
    int k0 = blockIdx.x * 128;
    const float* Am = g_T + (size_t)b * NNv * NNv;  // [k][n]
    const float* Bm = g_G + (size_t)b * NNv * CCv;  // [n][cc]
    float* Cm = g_H + (size_t)b * NNv * CCv;        // [k][cc]

    __shared__ float As[2][128][36];   // 36.9 KB
    __shared__ float Bs[2][32][136];   // 34.8 KB

    int t = threadIdx.x;
    int lane = t & 31, w = t >> 5;
    int g = lane >> 2, tg = lane & 3;
    int wm = (w & 3) * 32;
    int wn = (w >> 2) * 64;

    float c[2][8][4];
    #pragma unroll
    for (int i = 0; i < 2; i++)
        #pragma unroll
        for (int j = 0; j < 8; j++)
            #pragma unroll
            for (int e = 0; e < 4; e++) c[i][j][e] = 0.f;

    int s_arow = t >> 3, s_ac4 = (t & 7) * 4;     // A: 128x32, 4 passes of 256
    int s_brow = t >> 5, s_bc4 = (t & 31) * 4;    // B: 32x128, 4 passes of 256

    // stage tile 0 into buffer 0
    #pragma unroll
    for (int pass = 0; pass < 4; pass++) {
        int ar = s_arow + pass * 32;
        cpa16(&As[0][ar][s_ac4], Am + (size_t)(k0 + ar) * NNv + s_ac4);
        int br = s_brow + pass * 8;
        cpa16(&Bs[0][br][s_bc4], Bm + (size_t)br * CCv + cc0 + s_bc4);
    }
    asm volatile("cp.async.commit_group;");

    int buf = 0;
    for (int n0 = 0; n0 < NNv; n0 += 32) {
        bool has_next = (n0 + 32) < NNv;
        if (has_next) {
            int nb = buf ^ 1, nn0 = n0 + 32;
            #pragma unroll
            for (int pass = 0; pass < 4; pass++) {
                int ar = s_arow + pass * 32;
                cpa16(&As[nb][ar][s_ac4], Am + (size_t)(k0 + ar) * NNv + nn0 + s_ac4);
                int br = s_brow + pass * 8;
                cpa16(&Bs[nb][br][s_bc4], Bm + (size_t)(nn0 + br) * CCv + cc0 + s_bc4);
            }
            asm volatile("cp.async.commit_group;");
            asm volatile("cp.async.wait_group 1;");
        } else {
            asm volatile("cp.async.wait_group 0;");
        }
        __syncthreads();
        #pragma unroll
        for (int k8 = 0; k8 < 4; k8++) {
            unsigned a[2][4], bb[8][2];
            #pragma unroll
            for (int i = 0; i < 2; i++) {
                int r = wm + i * 16 + g;
                a[i][0] = __float_as_uint(As[buf][r][k8 * 8 + tg]);
                a[i][1] = __float_as_uint(As[buf][r + 8][k8 * 8 + tg]);
                a[i][2] = __float_as_uint(As[buf][r][k8 * 8 + tg + 4]);
                a[i][3] = __float_as_uint(As[buf][r + 8][k8 * 8 + tg + 4]);
            }
            #pragma unroll
            for (int j = 0; j < 8; j++) {
                bb[j][0] = __float_as_uint(Bs[buf][k8 * 8 + tg][wn + j * 8 + g]);
                bb[j][1] = __float_as_uint(Bs[buf][k8 * 8 + tg + 4][wn + j * 8 + g]);
            }
            #pragma unroll
            for (int i = 0; i < 2; i++)
                #pragma unroll
                for (int j = 0; j < 8; j++)
                    mma_tf32(c[i][j], a[i], bb[j]);
        }
        __syncthreads();
        buf ^= 1;
    }
    #pragma unroll
    for (int i = 0; i < 2; i++) {
        int r0 = k0 + wm + i * 16 + g;
        #pragma unroll
        for (int j = 0; j < 8; j++) {
            int col = cc0 + wn + j * 8 + tg * 2;
            *(float2*)(Cm + (size_t)r0 * CCv + col) =
                make_float2(c[i][j][0], c[i][j][1]);
            *(float2*)(Cm + (size_t)(r0 + 8) * CCv + col) =
                make_float2(c[i][j][2], c[i][j][3]);
        }
    }
}

// k4: block = (16-k chunk, b), 256 threads (256 CTAs -> fills the chip).
// Stage Wg once per block; phase1 xg, phase2 64x64x16 output GEMM.
__global__ void __launch_bounds__(256) k4(const float* __restrict__ Wg,
                                          const float* __restrict__ bg,
                                          float* __restrict__ out) {
    int k0 = blockIdx.x * 16, b = blockIdx.y;
    __shared__ float Wgs[C4v * 65];   // padded [o2][c]
    __shared__ float xg[16][65];
    __shared__ float Flk[16][OQ];
    int t = threadIdx.x;  // 256

    for (int i = t; i < C4v * C4v; i += 256)
        Wgs[(i >> 6) * 65 + (i & 63)] = Wg[i];
    if (t < 64)
        ((float4*)&Flk[0][0])[t] =
            ((const float4*)(g_Fl + ((size_t)b * NNv + k0) * OQ))[t];
    __syncthreads();

    float inv = g_invl2[b];
    {   // phase 1: thread -> (k = t/16, 4 c's)
        int k = t >> 4;
        int cg = (t & 15) * 4;
        const float4* Hrow =
            (const float4*)(g_H + ((size_t)b * NNv + k0 + k) * CCv);
        float s[4] = {0.f, 0.f, 0.f, 0.f};
        #pragma unroll 4
        for (int o = 0; o < OQ; o++) {
            float fl = Flk[k][o];
            float4 h = __ldg(Hrow + o * 16 + (cg >> 2));
            s[0] += fl * h.x; s[1] += fl * h.y;
            s[2] += fl * h.z; s[3] += fl * h.w;
        }
        #pragma unroll
        for (int j = 0; j < 4; j++) xg[k][cg + j] = s[j] * inv;
    }
    __syncthreads();
    {   // phase 2: thread -> (o2 = t/4, 4 k's)
        int o2 = t >> 2;
        int kg = (t & 3) * 4;
        float s[4];
        float bias = bg[o2];
        #pragma unroll
        for (int j = 0; j < 4; j++) s[j] = bias;
        #pragma unroll 8
        for (int c = 0; c < C4v; c++) {
            float w = Wgs[o2 * 65 + c];
            #pragma unroll
            for (int j = 0; j < 4; j++) s[j] += w * xg[kg + j][c];
        }
        float* dst = out + ((size_t)b * C4v + o2) * NNv + k0 + kg;
        #pragma unroll
        for (int j = 0; j < 4; j++) dst[j] = s[j];
    }
}

extern "C" void kernel_launch(void* const* d_in, const int* in_sizes, int n_in,
                              void* d_out, int out_size) {
    const float* x  = (const float*)d_in[0];
    const float* Wc = (const float*)d_in[1];
    const float* bc = (const float*)d_in[2];
    const float* Wg = (const float*)d_in[3];
    const float* bg = (const float*)d_in[4];
    float* out = (float*)d_out;

    k_zero<<<1, 256>>>();
    k1<<<dim3(NNv, BB), 128>>>(x, Wc, bc);
    k1b<<<BB, 32>>>();
    k2tc<<<dim3(NNv / 16, BB), 256>>>();
    k3<<<dim3(NNv / 128, CCv / 128, BB), 256>>>();
    k4<<<dim3(NNv / 16, BB), 256>>>(Wg, bg, out);
}